// round 1
// baseline (speedup 1.0000x reference)
#include <cuda_runtime.h>
#include <math.h>

// Problem constants
#define B_    4
#define T_    2048
#define C_    2048
#define H_    16
#define D_    128
#define NQKV_ 6144   // 3*C_
#define MROWS 8192   // B_*T_

// ---------------------------------------------------------------------------
// Scratch (device globals — no allocations allowed)
// ---------------------------------------------------------------------------
__device__ __align__(256) float g_Q[(size_t)B_ * H_ * T_ * D_];
__device__ __align__(256) float g_K[(size_t)B_ * H_ * T_ * D_];
__device__ __align__(256) float g_V[(size_t)B_ * H_ * T_ * D_];
__device__ __align__(256) float g_Y[(size_t)B_ * T_ * C_];
__device__ __align__(256) float g_cos[T_ * 64];
__device__ __align__(256) float g_sin[T_ * 64];

// ---------------------------------------------------------------------------
// TF32 helpers (3xTF32: x = hi + lo, D += ah*bl + al*bh + ah*bh)
// ---------------------------------------------------------------------------
__device__ __forceinline__ unsigned f2tf(float x) {
    unsigned u;
    asm("cvt.rna.tf32.f32 %0, %1;" : "=r"(u) : "f"(x));
    return u;
}

__device__ __forceinline__ void split_tf32(float x, unsigned& hi, unsigned& lo) {
    unsigned h;
    asm("cvt.rna.tf32.f32 %0, %1;" : "=r"(h) : "f"(x));
    float r = x - __uint_as_float(h);
    unsigned l;
    asm("cvt.rna.tf32.f32 %0, %1;" : "=r"(l) : "f"(r));
    hi = h; lo = l;
}

__device__ __forceinline__ void mma_tf32(float c[4], const unsigned a[4], const unsigned b[2]) {
    asm volatile(
        "mma.sync.aligned.m16n8k8.row.col.f32.tf32.tf32.f32 "
        "{%0,%1,%2,%3}, {%4,%5,%6,%7}, {%8,%9}, {%0,%1,%2,%3};"
        : "+f"(c[0]), "+f"(c[1]), "+f"(c[2]), "+f"(c[3])
        : "r"(a[0]), "r"(a[1]), "r"(a[2]), "r"(a[3]), "r"(b[0]), "r"(b[1]));
}

__device__ __forceinline__ void mma_3x(float c[4],
                                       const unsigned ah[4], const unsigned al[4],
                                       const unsigned bh[2], const unsigned bl[2]) {
    mma_tf32(c, ah, bl);
    mma_tf32(c, al, bh);
    mma_tf32(c, ah, bh);
}

// ---------------------------------------------------------------------------
// RoPE tables: angle computed exactly like the float32 reference (float mult),
// trig evaluated in double for accuracy.
// ---------------------------------------------------------------------------
__global__ void rope_table_kernel() {
    int i = blockIdx.x * blockDim.x + threadIdx.x;
    if (i >= T_ * 64) return;
    int t = i >> 6, d = i & 63;
    float invf = powf(10000.0f, -(float)d / 64.0f);
    float ang = (float)t * invf;
    g_cos[i] = (float)cos((double)ang);
    g_sin[i] = (float)sin((double)ang);
}

// ---------------------------------------------------------------------------
// RoPE apply (in place on g_Q / g_K), fold 1/sqrt(D) into Q.
// ---------------------------------------------------------------------------
__global__ void rope_apply_kernel() {
    int i = blockIdx.x * blockDim.x + threadIdx.x;
    const int total = B_ * H_ * T_ * 64;
    if (i >= total) return;
    int d  = i & 63;
    int t  = (i >> 6) & (T_ - 1);
    int bh = i >> 17;  // 64*2048 = 2^17
    size_t base = ((size_t)bh * T_ + t) * D_;
    float c = g_cos[(t << 6) + d];
    float s = g_sin[(t << 6) + d];
    const float scale = 0.08838834764831845f;  // 1/sqrt(128)
    float q1 = g_Q[base + d], q2 = g_Q[base + d + 64];
    g_Q[base + d]      = (q1 * c - q2 * s) * scale;
    g_Q[base + d + 64] = (q2 * c + q1 * s) * scale;
    float k1 = g_K[base + d], k2 = g_K[base + d + 64];
    g_K[base + d]      = k1 * c - k2 * s;
    g_K[base + d + 64] = k2 * c + k1 * s;
}

// ---------------------------------------------------------------------------
// 3xTF32 GEMM: C[M,N] = A[M,K] @ B[K,N]   (row-major)
// MODE 1: A = x param, epilogue scatters into g_Q/g_K/g_V ([B,H,T,D] layout)
// MODE 2: A = g_Y, epilogue plain write to C param
// Tiles: BM=128, BN=128, BK=16, 256 threads (8 warps, 4x2, warp tile 32x64)
// ---------------------------------------------------------------------------
#define GBM 128
#define GBN 128
#define GBK 16

__device__ __forceinline__ void store_qkv(int r, int c, float val) {
    int b = r >> 11, t = r & 2047;
    int sec = c >> 11, cc = c & 2047;
    int h = cc >> 7, d = cc & 127;
    size_t dst = (((size_t)(b * H_ + h)) * T_ + t) * D_ + d;
    if (sec == 0)      g_Q[dst] = val;
    else if (sec == 1) g_K[dst] = val;
    else               g_V[dst] = val;
}

template <int MODE>
__global__ void __launch_bounds__(256) gemm_tf32x3_kernel(
    const float* __restrict__ A_in, const float* __restrict__ B_in,
    float* __restrict__ C, int M, int N, int K)
{
    __shared__ float As[2][GBK][GBM + 4];
    __shared__ float Bs[2][GBK][GBN + 4];

    const float* A = (MODE == 2) ? (const float*)g_Y : A_in;

    const int tid = threadIdx.x;
    const int lane = tid & 31, warp = tid >> 5;
    const int warpM = warp >> 1, warpN = warp & 1;
    const int gid = lane >> 2, t4 = lane & 3;
    const int bm = blockIdx.y * GBM, bn = blockIdx.x * GBN;

    float acc[2][8][4];
#pragma unroll
    for (int mi = 0; mi < 2; mi++)
#pragma unroll
        for (int ni = 0; ni < 8; ni++)
#pragma unroll
            for (int q = 0; q < 4; q++) acc[mi][ni][q] = 0.f;

    const int arow = tid >> 2;          // 0..63
    const int ac4  = (tid & 3) * 4;     // 0,4,8,12
    const int bk   = tid >> 5;          // 0..7
    const int bc4  = (tid & 31) * 4;    // 0..124

    const float* Aptr  = A + (size_t)(bm + arow) * K;
    const float* Aptr2 = A + (size_t)(bm + arow + 64) * K;
    const float* Bptr  = B_in + (size_t)bk * N + bn + bc4;
    const float* Bptr2 = B_in + (size_t)(bk + 8) * N + bn + bc4;

    const int nk = K / GBK;

    // prologue: tile 0
    float4 av0 = *(const float4*)(Aptr + ac4);
    float4 av1 = *(const float4*)(Aptr2 + ac4);
    float4 bv0 = *(const float4*)(Bptr);
    float4 bv1 = *(const float4*)(Bptr2);
#pragma unroll
    for (int i = 0; i < 4; i++) {
        As[0][ac4 + i][arow]      = (&av0.x)[i];
        As[0][ac4 + i][arow + 64] = (&av1.x)[i];
    }
    *(float4*)&Bs[0][bk][bc4]     = bv0;
    *(float4*)&Bs[0][bk + 8][bc4] = bv1;
    __syncthreads();

    for (int kt = 0; kt < nk; kt++) {
        const int cur = kt & 1, nxt = cur ^ 1;
        if (kt + 1 < nk) {
            av0 = *(const float4*)(Aptr  + (kt + 1) * GBK + ac4);
            av1 = *(const float4*)(Aptr2 + (kt + 1) * GBK + ac4);
            bv0 = *(const float4*)(Bptr  + (size_t)(kt + 1) * GBK * N);
            bv1 = *(const float4*)(Bptr2 + (size_t)(kt + 1) * GBK * N);
        }
#pragma unroll
        for (int ks = 0; ks < GBK; ks += 8) {
            unsigned ah[2][4], al[2][4], bh[8][2], bl[8][2];
#pragma unroll
            for (int mi = 0; mi < 2; mi++) {
                int mr = warpM * 32 + mi * 16;
                split_tf32(As[cur][ks + t4][mr + gid],          ah[mi][0], al[mi][0]);
                split_tf32(As[cur][ks + t4][mr + 8 + gid],      ah[mi][1], al[mi][1]);
                split_tf32(As[cur][ks + 4 + t4][mr + gid],      ah[mi][2], al[mi][2]);
                split_tf32(As[cur][ks + 4 + t4][mr + 8 + gid],  ah[mi][3], al[mi][3]);
            }
#pragma unroll
            for (int ni = 0; ni < 8; ni++) {
                int nc = warpN * 64 + ni * 8 + gid;
                split_tf32(Bs[cur][ks + t4][nc],     bh[ni][0], bl[ni][0]);
                split_tf32(Bs[cur][ks + 4 + t4][nc], bh[ni][1], bl[ni][1]);
            }
#pragma unroll
            for (int mi = 0; mi < 2; mi++)
#pragma unroll
                for (int ni = 0; ni < 8; ni++)
                    mma_3x(acc[mi][ni], ah[mi], al[mi], bh[ni], bl[ni]);
        }
        if (kt + 1 < nk) {
#pragma unroll
            for (int i = 0; i < 4; i++) {
                As[nxt][ac4 + i][arow]      = (&av0.x)[i];
                As[nxt][ac4 + i][arow + 64] = (&av1.x)[i];
            }
            *(float4*)&Bs[nxt][bk][bc4]     = bv0;
            *(float4*)&Bs[nxt][bk + 8][bc4] = bv1;
        }
        __syncthreads();
    }

    // epilogue
#pragma unroll
    for (int mi = 0; mi < 2; mi++) {
#pragma unroll
        for (int ni = 0; ni < 8; ni++) {
            int r0 = bm + warpM * 32 + mi * 16 + gid;
            int c0 = bn + warpN * 64 + ni * 8 + t4 * 2;
            if (MODE == 1) {
                store_qkv(r0,     c0,     acc[mi][ni][0]);
                store_qkv(r0,     c0 + 1, acc[mi][ni][1]);
                store_qkv(r0 + 8, c0,     acc[mi][ni][2]);
                store_qkv(r0 + 8, c0 + 1, acc[mi][ni][3]);
            } else {
                C[(size_t)r0 * N + c0]           = acc[mi][ni][0];
                C[(size_t)r0 * N + c0 + 1]       = acc[mi][ni][1];
                C[(size_t)(r0 + 8) * N + c0]     = acc[mi][ni][2];
                C[(size_t)(r0 + 8) * N + c0 + 1] = acc[mi][ni][3];
            }
        }
    }
}

// ---------------------------------------------------------------------------
// Flash attention, causal, 3xTF32. Br=128 (8 warps x 16 rows), Bc=64, D=128.
// grid = (T/128, B*H), 256 threads, ~166KB dynamic smem.
// ---------------------------------------------------------------------------
#define ATT_QSTRIDE 132
#define ATT_PSTRIDE 68
#define ATT_SMEM_FLOATS (128 * ATT_QSTRIDE + 64 * ATT_QSTRIDE + 64 * ATT_QSTRIDE + 128 * ATT_PSTRIDE)
#define ATT_SMEM_BYTES (ATT_SMEM_FLOATS * 4)

__global__ void __launch_bounds__(256) attn_kernel() {
    extern __shared__ float sm_att[];
    float* Qs = sm_att;                        // [128][132]
    float* Ks = Qs + 128 * ATT_QSTRIDE;        // [64][132]
    float* Vs = Ks + 64 * ATT_QSTRIDE;         // [64][132]
    float* Ps = Vs + 64 * ATT_QSTRIDE;         // [128][68]

    const int tid = threadIdx.x;
    const int lane = tid & 31, w = tid >> 5;
    const int gid = lane >> 2, t4 = lane & 3;
    const int qtile = blockIdx.x, bh = blockIdx.y;
    const int qbase = qtile * 128;

    const float* Qg = g_Q + ((size_t)bh * T_ + qbase) * D_;
    const float* Kg = g_K + (size_t)bh * T_ * D_;
    const float* Vg = g_V + (size_t)bh * T_ * D_;

    // Load Q tile (128x128)
#pragma unroll
    for (int i = 0; i < 16; i++) {
        int idx = tid + i * 256;               // 0..4095 float4s
        int row = idx >> 5, c4 = (idx & 31) << 2;
        *(float4*)&Qs[row * ATT_QSTRIDE + c4] = *(const float4*)(Qg + (size_t)row * D_ + c4);
    }

    float o[16][4];
#pragma unroll
    for (int a = 0; a < 16; a++)
#pragma unroll
        for (int c = 0; c < 4; c++) o[a][c] = 0.f;
    float m0 = -1e30f, m1 = -1e30f, l0 = 0.f, l1 = 0.f;

    const int mrow = w * 16;
    const int rl0 = mrow + gid, rl1 = mrow + gid + 8;
    const int njt = 2 * qtile + 2;

    for (int j = 0; j < njt; j++) {
        __syncthreads();
#pragma unroll
        for (int i = 0; i < 8; i++) {
            int idx = tid + i * 256;           // 0..2047 float4s
            int row = idx >> 5, c4 = (idx & 31) << 2;
            float4 kv = *(const float4*)(Kg + ((size_t)j * 64 + row) * D_ + c4);
            float4 vv = *(const float4*)(Vg + ((size_t)j * 64 + row) * D_ + c4);
            *(float4*)&Ks[row * ATT_QSTRIDE + c4] = kv;
            *(float4*)&Vs[row * ATT_QSTRIDE + c4] = vv;
        }
        __syncthreads();

        // S = Q K^T (64 cols), 3xTF32
        float s[8][4];
#pragma unroll
        for (int ni = 0; ni < 8; ni++)
#pragma unroll
            for (int q = 0; q < 4; q++) s[ni][q] = 0.f;

#pragma unroll 2
        for (int ks = 0; ks < 128; ks += 8) {
            unsigned ah[4], al[4];
            split_tf32(Qs[rl0 * ATT_QSTRIDE + ks + t4],     ah[0], al[0]);
            split_tf32(Qs[rl1 * ATT_QSTRIDE + ks + t4],     ah[1], al[1]);
            split_tf32(Qs[rl0 * ATT_QSTRIDE + ks + 4 + t4], ah[2], al[2]);
            split_tf32(Qs[rl1 * ATT_QSTRIDE + ks + 4 + t4], ah[3], al[3]);
#pragma unroll
            for (int ni = 0; ni < 8; ni++) {
                unsigned bh_[2], bl_[2];
                split_tf32(Ks[(ni * 8 + gid) * ATT_QSTRIDE + ks + t4],     bh_[0], bl_[0]);
                split_tf32(Ks[(ni * 8 + gid) * ATT_QSTRIDE + ks + 4 + t4], bh_[1], bl_[1]);
                mma_3x(s[ni], ah, al, bh_, bl_);
            }
        }

        // Causal mask (only tiles intersecting the diagonal)
        if (j >= 2 * qtile) {
            const int rg0 = qbase + rl0, rg1 = qbase + rl1;
#pragma unroll
            for (int ni = 0; ni < 8; ni++) {
                int cg = j * 64 + ni * 8 + t4 * 2;
                if (cg     > rg0) s[ni][0] = -1e30f;
                if (cg + 1 > rg0) s[ni][1] = -1e30f;
                if (cg     > rg1) s[ni][2] = -1e30f;
                if (cg + 1 > rg1) s[ni][3] = -1e30f;
            }
        }

        // Online softmax (rows rl0 / rl1; quad = lanes sharing gid)
        float rmax0 = -1e30f, rmax1 = -1e30f;
#pragma unroll
        for (int ni = 0; ni < 8; ni++) {
            rmax0 = fmaxf(rmax0, fmaxf(s[ni][0], s[ni][1]));
            rmax1 = fmaxf(rmax1, fmaxf(s[ni][2], s[ni][3]));
        }
        rmax0 = fmaxf(rmax0, __shfl_xor_sync(0xffffffffu, rmax0, 1));
        rmax0 = fmaxf(rmax0, __shfl_xor_sync(0xffffffffu, rmax0, 2));
        rmax1 = fmaxf(rmax1, __shfl_xor_sync(0xffffffffu, rmax1, 1));
        rmax1 = fmaxf(rmax1, __shfl_xor_sync(0xffffffffu, rmax1, 2));

        float nm0 = fmaxf(m0, rmax0), nm1 = fmaxf(m1, rmax1);
        float a0 = __expf(m0 - nm0), a1 = __expf(m1 - nm1);
        m0 = nm0; m1 = nm1;

        float sum0 = 0.f, sum1 = 0.f;
#pragma unroll
        for (int ni = 0; ni < 8; ni++) {
            s[ni][0] = __expf(s[ni][0] - nm0);
            s[ni][1] = __expf(s[ni][1] - nm0);
            s[ni][2] = __expf(s[ni][2] - nm1);
            s[ni][3] = __expf(s[ni][3] - nm1);
            sum0 += s[ni][0] + s[ni][1];
            sum1 += s[ni][2] + s[ni][3];
        }
        sum0 += __shfl_xor_sync(0xffffffffu, sum0, 1);
        sum0 += __shfl_xor_sync(0xffffffffu, sum0, 2);
        sum1 += __shfl_xor_sync(0xffffffffu, sum1, 1);
        sum1 += __shfl_xor_sync(0xffffffffu, sum1, 2);
        l0 = l0 * a0 + sum0;
        l1 = l1 * a1 + sum1;

#pragma unroll
        for (int di = 0; di < 16; di++) {
            o[di][0] *= a0; o[di][1] *= a0;
            o[di][2] *= a1; o[di][3] *= a1;
        }

        // P to smem (per-warp region; same warp consumes)
#pragma unroll
        for (int ni = 0; ni < 8; ni++) {
            Ps[rl0 * ATT_PSTRIDE + ni * 8 + t4 * 2]     = s[ni][0];
            Ps[rl0 * ATT_PSTRIDE + ni * 8 + t4 * 2 + 1] = s[ni][1];
            Ps[rl1 * ATT_PSTRIDE + ni * 8 + t4 * 2]     = s[ni][2];
            Ps[rl1 * ATT_PSTRIDE + ni * 8 + t4 * 2 + 1] = s[ni][3];
        }
        __syncwarp();

        // O += P @ V (3xTF32)
#pragma unroll 2
        for (int kk = 0; kk < 64; kk += 8) {
            unsigned ah[4], al[4];
            split_tf32(Ps[rl0 * ATT_PSTRIDE + kk + t4],     ah[0], al[0]);
            split_tf32(Ps[rl1 * ATT_PSTRIDE + kk + t4],     ah[1], al[1]);
            split_tf32(Ps[rl0 * ATT_PSTRIDE + kk + 4 + t4], ah[2], al[2]);
            split_tf32(Ps[rl1 * ATT_PSTRIDE + kk + 4 + t4], ah[3], al[3]);
#pragma unroll
            for (int di = 0; di < 16; di++) {
                unsigned bh_[2], bl_[2];
                split_tf32(Vs[(kk + t4) * ATT_QSTRIDE + di * 8 + gid],     bh_[0], bl_[0]);
                split_tf32(Vs[(kk + 4 + t4) * ATT_QSTRIDE + di * 8 + gid], bh_[1], bl_[1]);
                mma_3x(o[di], ah, al, bh_, bl_);
            }
        }
        __syncwarp();
    }

    // Normalize + write to g_Y [B,T,C]
    float il0 = 1.0f / l0, il1 = 1.0f / l1;
    int b = bh >> 4, h = bh & 15;
    int rg0 = qbase + rl0, rg1 = qbase + rl1;
#pragma unroll
    for (int di = 0; di < 16; di++) {
        size_t base0 = ((size_t)b * T_ + rg0) * C_ + h * D_ + di * 8 + t4 * 2;
        size_t base1 = ((size_t)b * T_ + rg1) * C_ + h * D_ + di * 8 + t4 * 2;
        g_Y[base0]     = o[di][0] * il0;
        g_Y[base0 + 1] = o[di][1] * il0;
        g_Y[base1]     = o[di][2] * il1;
        g_Y[base1 + 1] = o[di][3] * il1;
    }
}

// ---------------------------------------------------------------------------
// Launch
// ---------------------------------------------------------------------------
extern "C" void kernel_launch(void* const* d_in, const int* in_sizes, int n_in,
                              void* d_out, int out_size) {
    const float* x      = (const float*)d_in[0];  // [4,2048,2048]
    const float* w_attn = (const float*)d_in[1];  // [2048,6144]
    const float* w_proj = (const float*)d_in[2];  // [2048,2048]
    float* out = (float*)d_out;                   // [4,2048,2048]

    (void)in_sizes; (void)n_in; (void)out_size;

    cudaFuncSetAttribute(attn_kernel, cudaFuncAttributeMaxDynamicSharedMemorySize,
                         ATT_SMEM_BYTES);

    // 1. RoPE tables
    rope_table_kernel<<<(T_ * 64 + 255) / 256, 256>>>();

    // 2. QKV GEMM (x @ w_attn) -> g_Q/g_K/g_V in [B,H,T,D]
    gemm_tf32x3_kernel<1><<<dim3(NQKV_ / GBN, MROWS / GBM), 256>>>(
        x, w_attn, nullptr, MROWS, NQKV_, C_);

    // 3. RoPE + scale fold
    rope_apply_kernel<<<(B_ * H_ * T_ * 64 + 255) / 256, 256>>>();

    // 4. Causal flash attention -> g_Y [B,T,C]
    attn_kernel<<<dim3(T_ / 128, B_ * H_), 256, ATT_SMEM_BYTES>>>();

    // 5. Output projection (g_Y @ w_proj) -> d_out
    gemm_tf32x3_kernel<2><<<dim3(C_ / GBN, MROWS / GBM), 256>>>(
        nullptr, w_proj, out, MROWS, C_, C_);
}

// round 2
// speedup vs baseline: 2.0667x; 2.0667x over previous
#include <cuda_runtime.h>
#include <cuda_bf16.h>
#include <math.h>

// Problem constants
#define B_    4
#define T_    2048
#define C_    2048
#define H_    16
#define D_    128
#define NQKV_ 6144   // 3*C_
#define MROWS 8192   // B_*T_

// ---------------------------------------------------------------------------
// Scratch (device globals — no allocations allowed)
// ---------------------------------------------------------------------------
__device__ __align__(256) float g_Q[(size_t)B_ * H_ * T_ * D_];
__device__ __align__(256) float g_K[(size_t)B_ * H_ * T_ * D_];
__device__ __align__(256) float g_V[(size_t)B_ * H_ * T_ * D_];
__device__ __align__(256) float g_Y[(size_t)B_ * T_ * C_];
__device__ __align__(256) float g_cos[T_ * 64];
__device__ __align__(256) float g_sin[T_ * 64];

// ---------------------------------------------------------------------------
// bf16x3 helpers: x = hi + lo (two bf16), D += ah*bl + al*bh + ah*bh
// ---------------------------------------------------------------------------
__device__ __forceinline__ void split_pair(float x0, float x1, unsigned& h, unsigned& l) {
    __nv_bfloat16 h0 = __float2bfloat16_rn(x0);
    __nv_bfloat16 h1 = __float2bfloat16_rn(x1);
    __nv_bfloat16 l0 = __float2bfloat16_rn(x0 - __bfloat162float(h0));
    __nv_bfloat16 l1 = __float2bfloat16_rn(x1 - __bfloat162float(h1));
    __nv_bfloat162 hh = __halves2bfloat162(h0, h1);
    __nv_bfloat162 ll = __halves2bfloat162(l0, l1);
    h = *reinterpret_cast<unsigned*>(&hh);
    l = *reinterpret_cast<unsigned*>(&ll);
}

__device__ __forceinline__ void mma_bf16(float c[4], const unsigned a[4], const unsigned b[2]) {
    asm volatile(
        "mma.sync.aligned.m16n8k16.row.col.f32.bf16.bf16.f32 "
        "{%0,%1,%2,%3}, {%4,%5,%6,%7}, {%8,%9}, {%0,%1,%2,%3};"
        : "+f"(c[0]), "+f"(c[1]), "+f"(c[2]), "+f"(c[3])
        : "r"(a[0]), "r"(a[1]), "r"(a[2]), "r"(a[3]), "r"(b[0]), "r"(b[1]));
}

__device__ __forceinline__ void mma_3x(float c[4],
                                       const unsigned ah[4], const unsigned al[4],
                                       const unsigned bh[2], const unsigned bl[2]) {
    mma_bf16(c, ah, bl);
    mma_bf16(c, al, bh);
    mma_bf16(c, ah, bh);
}

// ---------------------------------------------------------------------------
// RoPE tables
// ---------------------------------------------------------------------------
__global__ void rope_table_kernel() {
    int i = blockIdx.x * blockDim.x + threadIdx.x;
    if (i >= T_ * 64) return;
    int t = i >> 6, d = i & 63;
    float invf = powf(10000.0f, -(float)d / 64.0f);
    float ang = (float)t * invf;
    g_cos[i] = (float)cos((double)ang);
    g_sin[i] = (float)sin((double)ang);
}

// ---------------------------------------------------------------------------
// RoPE apply (in place on g_Q / g_K), fold 1/sqrt(D) into Q.
// ---------------------------------------------------------------------------
__global__ void rope_apply_kernel() {
    int i = blockIdx.x * blockDim.x + threadIdx.x;
    const int total = B_ * H_ * T_ * 64;
    if (i >= total) return;
    int d  = i & 63;
    int t  = (i >> 6) & (T_ - 1);
    int bh = i >> 17;
    size_t base = ((size_t)bh * T_ + t) * D_;
    float c = g_cos[(t << 6) + d];
    float s = g_sin[(t << 6) + d];
    const float scale = 0.08838834764831845f;  // 1/sqrt(128)
    float q1 = g_Q[base + d], q2 = g_Q[base + d + 64];
    g_Q[base + d]      = (q1 * c - q2 * s) * scale;
    g_Q[base + d + 64] = (q2 * c + q1 * s) * scale;
    float k1 = g_K[base + d], k2 = g_K[base + d + 64];
    g_K[base + d]      = k1 * c - k2 * s;
    g_K[base + d + 64] = k2 * c + k1 * s;
}

// ---------------------------------------------------------------------------
// bf16x3 GEMM: C[M,N] = A[M,K] @ B[K,N] (row-major fp32 in/out)
// Split to bf16 hi/lo at smem-store time. BM=128, BN=128, BK=32, 256 thr.
// A smem: [128][40] halves (k contiguous). B smem: [128 n][40 k] (transposed).
// MODE 1: epilogue scatters into g_Q/g_K/g_V.  MODE 2: A = g_Y, plain C write.
// ---------------------------------------------------------------------------
#define GBM 128
#define GBN 128
#define GBK 32
#define GST 40
#define GTILE (128 * GST)
#define GEMM_SMEM_BYTES (2 * 4 * GTILE * 2)   // 2 stages * 4 tiles * halves*2B

__device__ __forceinline__ void store_qkv(int r, int c, float val) {
    int b = r >> 11, t = r & 2047;
    int sec = c >> 11, cc = c & 2047;
    int h = cc >> 7, d = cc & 127;
    size_t dst = (((size_t)(b * H_ + h)) * T_ + t) * D_ + d;
    if (sec == 0)      g_Q[dst] = val;
    else if (sec == 1) g_K[dst] = val;
    else               g_V[dst] = val;
}

template <int MODE>
__global__ void __launch_bounds__(256) gemm_bf16x3_kernel(
    const float* __restrict__ A_in, const float* __restrict__ B_in,
    float* __restrict__ C, int M, int N, int K)
{
    extern __shared__ __align__(16) __nv_bfloat16 smg[];
    const float* A = (MODE == 2) ? (const float*)g_Y : A_in;

    const int tid = threadIdx.x;
    const int lane = tid & 31, warp = tid >> 5;
    const int warpM = warp >> 1, warpN = warp & 1;
    const int gid = lane >> 2, t4 = lane & 3;
    const int bm = blockIdx.y * GBM, bn = blockIdx.x * GBN;

    float acc[2][8][4];
#pragma unroll
    for (int mi = 0; mi < 2; mi++)
#pragma unroll
        for (int ni = 0; ni < 8; ni++)
#pragma unroll
            for (int q = 0; q < 4; q++) acc[mi][ni][q] = 0.f;

    // loader geometry (constant per thread)
    const int a_row0 = tid >> 3;          // + i*32
    const int a_c4   = (tid & 7) * 4;
    const int b_n    = tid & 127;         // column of B tile
    const int b_k0b  = (tid >> 7) * 4;    // + i*8

    const int nk = K / GBK;

    float4 pa[4];
    float  pb[16];

    // ---- prefetch tile kt into registers
#define G_PREFETCH(kt) do {                                                        \
    _Pragma("unroll")                                                              \
    for (int i = 0; i < 4; i++)                                                    \
        pa[i] = *(const float4*)(A + (size_t)(bm + a_row0 + i * 32) * K            \
                                   + (kt) * GBK + a_c4);                           \
    _Pragma("unroll")                                                              \
    for (int i = 0; i < 4; i++) {                                                  \
        const float* bp = B_in + (size_t)((kt) * GBK + b_k0b + i * 8) * N + bn + b_n; \
        pb[i*4+0] = bp[0]; pb[i*4+1] = bp[N];                                      \
        pb[i*4+2] = bp[2*(size_t)N]; pb[i*4+3] = bp[3*(size_t)N];                  \
    }                                                                              \
} while (0)

    // ---- split registers into stage s
#define G_STORE(s) do {                                                            \
    __nv_bfloat16* Ah = smg + (s) * 4 * GTILE;                                     \
    __nv_bfloat16* Al = Ah + GTILE;                                                \
    __nv_bfloat16* Bh = Al + GTILE;                                                \
    __nv_bfloat16* Bl = Bh + GTILE;                                                \
    _Pragma("unroll")                                                              \
    for (int i = 0; i < 4; i++) {                                                  \
        int row = a_row0 + i * 32;                                                 \
        unsigned h01, l01, h23, l23;                                               \
        split_pair(pa[i].x, pa[i].y, h01, l01);                                    \
        split_pair(pa[i].z, pa[i].w, h23, l23);                                    \
        *(unsigned*)&Ah[row * GST + a_c4]     = h01;                               \
        *(unsigned*)&Ah[row * GST + a_c4 + 2] = h23;                               \
        *(unsigned*)&Al[row * GST + a_c4]     = l01;                               \
        *(unsigned*)&Al[row * GST + a_c4 + 2] = l23;                               \
    }                                                                              \
    _Pragma("unroll")                                                              \
    for (int i = 0; i < 4; i++) {                                                  \
        int k0 = b_k0b + i * 8;                                                    \
        unsigned h01, l01, h23, l23;                                               \
        split_pair(pb[i*4+0], pb[i*4+1], h01, l01);                                \
        split_pair(pb[i*4+2], pb[i*4+3], h23, l23);                                \
        *(unsigned*)&Bh[b_n * GST + k0]     = h01;                                 \
        *(unsigned*)&Bh[b_n * GST + k0 + 2] = h23;                                 \
        *(unsigned*)&Bl[b_n * GST + k0]     = l01;                                 \
        *(unsigned*)&Bl[b_n * GST + k0 + 2] = l23;                                 \
    }                                                                              \
} while (0)

    G_PREFETCH(0);
    G_STORE(0);
    __syncthreads();

    for (int kt = 0; kt < nk; kt++) {
        const int cur = kt & 1;
        if (kt + 1 < nk) G_PREFETCH(kt + 1);

        {
            const __nv_bfloat16* Ah = smg + cur * 4 * GTILE;
            const __nv_bfloat16* Al = Ah + GTILE;
            const __nv_bfloat16* Bh = Al + GTILE;
            const __nv_bfloat16* Bl = Bh + GTILE;
#pragma unroll
            for (int ks = 0; ks < GBK; ks += 16) {
                unsigned ah[2][4], al[2][4];
#pragma unroll
                for (int mi = 0; mi < 2; mi++) {
                    int r0 = warpM * 32 + mi * 16 + gid;
                    int ko = ks + 2 * t4;
                    ah[mi][0] = *(const unsigned*)&Ah[r0 * GST + ko];
                    ah[mi][1] = *(const unsigned*)&Ah[(r0 + 8) * GST + ko];
                    ah[mi][2] = *(const unsigned*)&Ah[r0 * GST + ko + 8];
                    ah[mi][3] = *(const unsigned*)&Ah[(r0 + 8) * GST + ko + 8];
                    al[mi][0] = *(const unsigned*)&Al[r0 * GST + ko];
                    al[mi][1] = *(const unsigned*)&Al[(r0 + 8) * GST + ko];
                    al[mi][2] = *(const unsigned*)&Al[r0 * GST + ko + 8];
                    al[mi][3] = *(const unsigned*)&Al[(r0 + 8) * GST + ko + 8];
                }
#pragma unroll
                for (int ni = 0; ni < 8; ni++) {
                    int nc = warpN * 64 + ni * 8 + gid;
                    int ko = ks + 2 * t4;
                    unsigned bh[2], bl[2];
                    bh[0] = *(const unsigned*)&Bh[nc * GST + ko];
                    bh[1] = *(const unsigned*)&Bh[nc * GST + ko + 8];
                    bl[0] = *(const unsigned*)&Bl[nc * GST + ko];
                    bl[1] = *(const unsigned*)&Bl[nc * GST + ko + 8];
#pragma unroll
                    for (int mi = 0; mi < 2; mi++)
                        mma_3x(acc[mi][ni], ah[mi], al[mi], bh, bl);
                }
            }
        }

        if (kt + 1 < nk) G_STORE(cur ^ 1);
        __syncthreads();
    }

    // epilogue
#pragma unroll
    for (int mi = 0; mi < 2; mi++) {
#pragma unroll
        for (int ni = 0; ni < 8; ni++) {
            int r0 = bm + warpM * 32 + mi * 16 + gid;
            int c0 = bn + warpN * 64 + ni * 8 + t4 * 2;
            if (MODE == 1) {
                store_qkv(r0,     c0,     acc[mi][ni][0]);
                store_qkv(r0,     c0 + 1, acc[mi][ni][1]);
                store_qkv(r0 + 8, c0,     acc[mi][ni][2]);
                store_qkv(r0 + 8, c0 + 1, acc[mi][ni][3]);
            } else {
                C[(size_t)r0 * N + c0]           = acc[mi][ni][0];
                C[(size_t)r0 * N + c0 + 1]       = acc[mi][ni][1];
                C[(size_t)(r0 + 8) * N + c0]     = acc[mi][ni][2];
                C[(size_t)(r0 + 8) * N + c0 + 1] = acc[mi][ni][3];
            }
        }
    }
#undef G_PREFETCH
#undef G_STORE
}

// ---------------------------------------------------------------------------
// Flash attention, causal, bf16x3. Br=128 (8 warps x 16 rows), Bc=64, D=128.
// Q/K in [row][k] bf16 hi/lo, V transposed [d][k], P [row][k].
// ---------------------------------------------------------------------------
#define AQS 136   // Q/K k-stride (halves)
#define AVS 72    // VT/P k-stride (halves)

#define O_QH 0
#define O_QL (O_QH + 128 * AQS)
#define O_KH (O_QL + 128 * AQS)
#define O_KL (O_KH + 64 * AQS)
#define O_VTH (O_KL + 64 * AQS)
#define O_VTL (O_VTH + 128 * AVS)
#define O_PH (O_VTL + 128 * AVS)
#define O_PL (O_PH + 128 * AVS)
#define ATT_SMEM_HALVES (O_PL + 128 * AVS)
#define ATT_SMEM_BYTES (ATT_SMEM_HALVES * 2)

__global__ void __launch_bounds__(256) attn_kernel() {
    extern __shared__ __align__(16) __nv_bfloat16 sa[];
    __nv_bfloat16* Qh  = sa + O_QH;
    __nv_bfloat16* Ql  = sa + O_QL;
    __nv_bfloat16* Kh  = sa + O_KH;
    __nv_bfloat16* Kl  = sa + O_KL;
    __nv_bfloat16* VTh = sa + O_VTH;
    __nv_bfloat16* VTl = sa + O_VTL;
    __nv_bfloat16* Ph  = sa + O_PH;
    __nv_bfloat16* Pl  = sa + O_PL;

    const int tid = threadIdx.x;
    const int lane = tid & 31, w = tid >> 5;
    const int gid = lane >> 2, t4 = lane & 3;
    const int qtile = blockIdx.x, bh = blockIdx.y;
    const int qbase = qtile * 128;

    const float* Qg = g_Q + ((size_t)bh * T_ + qbase) * D_;
    const float* Kg = g_K + (size_t)bh * T_ * D_;
    const float* Vg = g_V + (size_t)bh * T_ * D_;

    // Load + split Q tile (128 x 128)
#pragma unroll
    for (int i = 0; i < 16; i++) {
        int u = tid + i * 256;
        int row = u >> 5, c4 = (u & 31) << 2;
        float4 v = *(const float4*)(Qg + (size_t)row * D_ + c4);
        unsigned h01, l01, h23, l23;
        split_pair(v.x, v.y, h01, l01);
        split_pair(v.z, v.w, h23, l23);
        *(unsigned*)&Qh[row * AQS + c4]     = h01;
        *(unsigned*)&Qh[row * AQS + c4 + 2] = h23;
        *(unsigned*)&Ql[row * AQS + c4]     = l01;
        *(unsigned*)&Ql[row * AQS + c4 + 2] = l23;
    }

    float o[16][4];
#pragma unroll
    for (int a = 0; a < 16; a++)
#pragma unroll
        for (int c = 0; c < 4; c++) o[a][c] = 0.f;
    float m0 = -1e30f, m1 = -1e30f, l0 = 0.f, l1 = 0.f;

    const int mrow = w * 16;
    const int rl0 = mrow + gid, rl1 = mrow + gid + 8;
    const int njt = 2 * qtile + 2;

    for (int j = 0; j < njt; j++) {
        __syncthreads();
        // K tile: [64 rows][128 k]
#pragma unroll
        for (int i = 0; i < 8; i++) {
            int u = tid + i * 256;
            int row = u >> 5, c4 = (u & 31) << 2;
            float4 kv = *(const float4*)(Kg + ((size_t)j * 64 + row) * D_ + c4);
            unsigned h01, l01, h23, l23;
            split_pair(kv.x, kv.y, h01, l01);
            split_pair(kv.z, kv.w, h23, l23);
            *(unsigned*)&Kh[row * AQS + c4]     = h01;
            *(unsigned*)&Kh[row * AQS + c4 + 2] = h23;
            *(unsigned*)&Kl[row * AQS + c4]     = l01;
            *(unsigned*)&Kl[row * AQS + c4 + 2] = l23;
        }
        // V tile transposed: VT[d][k], k packed in pairs
#pragma unroll
        for (int i = 0; i < 8; i++) {
            int u = tid + i * 256;
            int d = u & 127, k0 = (u >> 7) << 2;
            float v0 = Vg[((size_t)j * 64 + k0)     * D_ + d];
            float v1 = Vg[((size_t)j * 64 + k0 + 1) * D_ + d];
            float v2 = Vg[((size_t)j * 64 + k0 + 2) * D_ + d];
            float v3 = Vg[((size_t)j * 64 + k0 + 3) * D_ + d];
            unsigned h01, l01, h23, l23;
            split_pair(v0, v1, h01, l01);
            split_pair(v2, v3, h23, l23);
            *(unsigned*)&VTh[d * AVS + k0]     = h01;
            *(unsigned*)&VTh[d * AVS + k0 + 2] = h23;
            *(unsigned*)&VTl[d * AVS + k0]     = l01;
            *(unsigned*)&VTl[d * AVS + k0 + 2] = l23;
        }
        __syncthreads();

        // S = Q K^T (128x64), bf16x3
        float s[8][4];
#pragma unroll
        for (int ni = 0; ni < 8; ni++)
#pragma unroll
            for (int q = 0; q < 4; q++) s[ni][q] = 0.f;

#pragma unroll
        for (int ks = 0; ks < 128; ks += 16) {
            int ko = ks + 2 * t4;
            unsigned ah[4], al[4];
            ah[0] = *(const unsigned*)&Qh[rl0 * AQS + ko];
            ah[1] = *(const unsigned*)&Qh[rl1 * AQS + ko];
            ah[2] = *(const unsigned*)&Qh[rl0 * AQS + ko + 8];
            ah[3] = *(const unsigned*)&Qh[rl1 * AQS + ko + 8];
            al[0] = *(const unsigned*)&Ql[rl0 * AQS + ko];
            al[1] = *(const unsigned*)&Ql[rl1 * AQS + ko];
            al[2] = *(const unsigned*)&Ql[rl0 * AQS + ko + 8];
            al[3] = *(const unsigned*)&Ql[rl1 * AQS + ko + 8];
#pragma unroll
            for (int ni = 0; ni < 8; ni++) {
                int nc = ni * 8 + gid;
                unsigned bhf[2], blf[2];
                bhf[0] = *(const unsigned*)&Kh[nc * AQS + ko];
                bhf[1] = *(const unsigned*)&Kh[nc * AQS + ko + 8];
                blf[0] = *(const unsigned*)&Kl[nc * AQS + ko];
                blf[1] = *(const unsigned*)&Kl[nc * AQS + ko + 8];
                mma_3x(s[ni], ah, al, bhf, blf);
            }
        }

        // Causal mask
        if (j >= 2 * qtile) {
            const int rg0 = qbase + rl0, rg1 = qbase + rl1;
#pragma unroll
            for (int ni = 0; ni < 8; ni++) {
                int cg = j * 64 + ni * 8 + t4 * 2;
                if (cg     > rg0) s[ni][0] = -1e30f;
                if (cg + 1 > rg0) s[ni][1] = -1e30f;
                if (cg     > rg1) s[ni][2] = -1e30f;
                if (cg + 1 > rg1) s[ni][3] = -1e30f;
            }
        }

        // Online softmax
        float rmax0 = -1e30f, rmax1 = -1e30f;
#pragma unroll
        for (int ni = 0; ni < 8; ni++) {
            rmax0 = fmaxf(rmax0, fmaxf(s[ni][0], s[ni][1]));
            rmax1 = fmaxf(rmax1, fmaxf(s[ni][2], s[ni][3]));
        }
        rmax0 = fmaxf(rmax0, __shfl_xor_sync(0xffffffffu, rmax0, 1));
        rmax0 = fmaxf(rmax0, __shfl_xor_sync(0xffffffffu, rmax0, 2));
        rmax1 = fmaxf(rmax1, __shfl_xor_sync(0xffffffffu, rmax1, 1));
        rmax1 = fmaxf(rmax1, __shfl_xor_sync(0xffffffffu, rmax1, 2));

        float nm0 = fmaxf(m0, rmax0), nm1 = fmaxf(m1, rmax1);
        float a0 = __expf(m0 - nm0), a1 = __expf(m1 - nm1);
        m0 = nm0; m1 = nm1;

        float sum0 = 0.f, sum1 = 0.f;
#pragma unroll
        for (int ni = 0; ni < 8; ni++) {
            s[ni][0] = __expf(s[ni][0] - nm0);
            s[ni][1] = __expf(s[ni][1] - nm0);
            s[ni][2] = __expf(s[ni][2] - nm1);
            s[ni][3] = __expf(s[ni][3] - nm1);
            sum0 += s[ni][0] + s[ni][1];
            sum1 += s[ni][2] + s[ni][3];
        }
        sum0 += __shfl_xor_sync(0xffffffffu, sum0, 1);
        sum0 += __shfl_xor_sync(0xffffffffu, sum0, 2);
        sum1 += __shfl_xor_sync(0xffffffffu, sum1, 1);
        sum1 += __shfl_xor_sync(0xffffffffu, sum1, 2);
        l0 = l0 * a0 + sum0;
        l1 = l1 * a1 + sum1;

#pragma unroll
        for (int di = 0; di < 16; di++) {
            o[di][0] *= a0; o[di][1] *= a0;
            o[di][2] *= a1; o[di][3] *= a1;
        }

        // P -> smem (split bf16 hi/lo, per-warp region)
#pragma unroll
        for (int ni = 0; ni < 8; ni++) {
            int cc = ni * 8 + 2 * t4;
            unsigned h01, lo01, h23, lo23;
            split_pair(s[ni][0], s[ni][1], h01, lo01);
            split_pair(s[ni][2], s[ni][3], h23, lo23);
            *(unsigned*)&Ph[rl0 * AVS + cc] = h01;
            *(unsigned*)&Pl[rl0 * AVS + cc] = lo01;
            *(unsigned*)&Ph[rl1 * AVS + cc] = h23;
            *(unsigned*)&Pl[rl1 * AVS + cc] = lo23;
        }
        __syncwarp();

        // O += P @ V (bf16x3); V supplied transposed as B operand
#pragma unroll
        for (int kk = 0; kk < 64; kk += 16) {
            int ko = kk + 2 * t4;
            unsigned ah[4], al[4];
            ah[0] = *(const unsigned*)&Ph[rl0 * AVS + ko];
            ah[1] = *(const unsigned*)&Ph[rl1 * AVS + ko];
            ah[2] = *(const unsigned*)&Ph[rl0 * AVS + ko + 8];
            ah[3] = *(const unsigned*)&Ph[rl1 * AVS + ko + 8];
            al[0] = *(const unsigned*)&Pl[rl0 * AVS + ko];
            al[1] = *(const unsigned*)&Pl[rl1 * AVS + ko];
            al[2] = *(const unsigned*)&Pl[rl0 * AVS + ko + 8];
            al[3] = *(const unsigned*)&Pl[rl1 * AVS + ko + 8];
#pragma unroll
            for (int di = 0; di < 16; di++) {
                int nc = di * 8 + gid;
                unsigned bhf[2], blf[2];
                bhf[0] = *(const unsigned*)&VTh[nc * AVS + ko];
                bhf[1] = *(const unsigned*)&VTh[nc * AVS + ko + 8];
                blf[0] = *(const unsigned*)&VTl[nc * AVS + ko];
                blf[1] = *(const unsigned*)&VTl[nc * AVS + ko + 8];
                mma_3x(o[di], ah, al, bhf, blf);
            }
        }
    }

    // Normalize + write to g_Y [B,T,C]
    float il0 = 1.0f / l0, il1 = 1.0f / l1;
    int b = bh >> 4, h = bh & 15;
    int rg0 = qbase + rl0, rg1 = qbase + rl1;
#pragma unroll
    for (int di = 0; di < 16; di++) {
        size_t base0 = ((size_t)b * T_ + rg0) * C_ + h * D_ + di * 8 + t4 * 2;
        size_t base1 = ((size_t)b * T_ + rg1) * C_ + h * D_ + di * 8 + t4 * 2;
        g_Y[base0]     = o[di][0] * il0;
        g_Y[base0 + 1] = o[di][1] * il0;
        g_Y[base1]     = o[di][2] * il1;
        g_Y[base1 + 1] = o[di][3] * il1;
    }
}

// ---------------------------------------------------------------------------
// Launch
// ---------------------------------------------------------------------------
extern "C" void kernel_launch(void* const* d_in, const int* in_sizes, int n_in,
                              void* d_out, int out_size) {
    const float* x      = (const float*)d_in[0];
    const float* w_attn = (const float*)d_in[1];
    const float* w_proj = (const float*)d_in[2];
    float* out = (float*)d_out;

    (void)in_sizes; (void)n_in; (void)out_size;

    static bool attr_set = false;
    cudaFuncSetAttribute(attn_kernel, cudaFuncAttributeMaxDynamicSharedMemorySize,
                         ATT_SMEM_BYTES);
    cudaFuncSetAttribute(gemm_bf16x3_kernel<1>,
                         cudaFuncAttributeMaxDynamicSharedMemorySize, GEMM_SMEM_BYTES);
    cudaFuncSetAttribute(gemm_bf16x3_kernel<2>,
                         cudaFuncAttributeMaxDynamicSharedMemorySize, GEMM_SMEM_BYTES);
    (void)attr_set;

    // 1. RoPE tables
    rope_table_kernel<<<(T_ * 64 + 255) / 256, 256>>>();

    // 2. QKV GEMM (x @ w_attn) -> g_Q/g_K/g_V in [B,H,T,D]
    gemm_bf16x3_kernel<1><<<dim3(NQKV_ / GBN, MROWS / GBM), 256, GEMM_SMEM_BYTES>>>(
        x, w_attn, nullptr, MROWS, NQKV_, C_);

    // 3. RoPE + scale fold
    rope_apply_kernel<<<(B_ * H_ * T_ * 64 + 255) / 256, 256>>>();

    // 4. Causal flash attention -> g_Y [B,T,C]
    attn_kernel<<<dim3(T_ / 128, B_ * H_), 256, ATT_SMEM_BYTES>>>();

    // 5. Output projection (g_Y @ w_proj) -> d_out
    gemm_bf16x3_kernel<2><<<dim3(C_ / GBN, MROWS / GBM), 256, GEMM_SMEM_BYTES>>>(
        nullptr, w_proj, out, MROWS, C_, C_);
}